// round 7
// baseline (speedup 1.0000x reference)
#include <cuda_runtime.h>
#include <cuda_bf16.h>
#include <stdint.h>
#include <string.h>
#include <math.h>

#define Bn 8
#define Cn 256
#define C2n 256
#define Hn 64
#define Wn 64
#define HWn 4096
#define KKn 9
#define Ktot 2304

// ---------------- device scratch ----------------
__device__ float g_offset[Bn * 18 * HWn];
__device__ float g_mask[Bn * KKn * HWn];
__device__ __align__(16) __nv_bfloat16 g_whi[C2n * Ktot];
__device__ __align__(16) __nv_bfloat16 g_wlo[C2n * Ktot];
__device__ __align__(16) __nv_bfloat16 g_omhi[32 * Ktot];
__device__ __align__(16) __nv_bfloat16 g_omlo[32 * Ktot];
// x transposed to NHWC, bf16 hi/lo split: xt[b][y][w][c]
__device__ __align__(16) __nv_bfloat16 g_xhi[(size_t)Bn * HWn * Cn];
__device__ __align__(16) __nv_bfloat16 g_xlo[(size_t)Bn * HWn * Cn];

// ---------------- warp-level MMA helpers ----------------
__device__ __forceinline__ void ldsm4(uint32_t addr, uint32_t r[4]) {
    asm volatile("ldmatrix.sync.aligned.m8n8.x4.shared.b16 {%0,%1,%2,%3}, [%4];"
                 : "=r"(r[0]), "=r"(r[1]), "=r"(r[2]), "=r"(r[3]) : "r"(addr));
}
__device__ __forceinline__ void mma16816(float d[4], const uint32_t a[4], const uint32_t b[2]) {
    asm volatile("mma.sync.aligned.m16n8k16.row.col.f32.bf16.bf16.f32 "
                 "{%0,%1,%2,%3}, {%4,%5,%6,%7}, {%8,%9}, {%0,%1,%2,%3};"
                 : "+f"(d[0]), "+f"(d[1]), "+f"(d[2]), "+f"(d[3])
                 : "r"(a[0]), "r"(a[1]), "r"(a[2]), "r"(a[3]), "r"(b[0]), "r"(b[1]));
}
__device__ __forceinline__ uint32_t smem_to_u32(const void* p) {
    uint32_t a;
    asm("{ .reg .u64 t; cvta.to.shared.u64 t, %1; cvt.u32.u64 %0, t; }" : "=r"(a) : "l"(p));
    return a;
}
__device__ __forceinline__ float2 bf2f(uint32_t u) {
    __nv_bfloat162 h = *reinterpret_cast<__nv_bfloat162*>(&u);
    return __bfloat1622float2(h);
}
// accumulate 8 channels: v[i] += w * (hi[i] + lo[i])
__device__ __forceinline__ void accum8(float v[8], uint4 h, uint4 l, float w) {
    float2 a, bb;
    a = bf2f(h.x); bb = bf2f(l.x); v[0] = fmaf(w, a.x + bb.x, v[0]); v[1] = fmaf(w, a.y + bb.y, v[1]);
    a = bf2f(h.y); bb = bf2f(l.y); v[2] = fmaf(w, a.x + bb.x, v[2]); v[3] = fmaf(w, a.y + bb.y, v[3]);
    a = bf2f(h.z); bb = bf2f(l.z); v[4] = fmaf(w, a.x + bb.x, v[4]); v[5] = fmaf(w, a.y + bb.y, v[5]);
    a = bf2f(h.w); bb = bf2f(l.w); v[6] = fmaf(w, a.x + bb.x, v[6]); v[7] = fmaf(w, a.y + bb.y, v[7]);
}
__device__ __forceinline__ uint32_t pack_hi(float a, float b, float& ra, float& rb) {
    __nv_bfloat16 ha = __float2bfloat16(a);
    __nv_bfloat16 hb = __float2bfloat16(b);
    ra = a - __bfloat162float(ha);
    rb = b - __bfloat162float(hb);
    __nv_bfloat162 p = __halves2bfloat162(ha, hb);
    return *reinterpret_cast<uint32_t*>(&p);
}
__device__ __forceinline__ uint32_t pack_bf2(float a, float b) {
    __nv_bfloat162 p = __floats2bfloat162_rn(a, b);
    return *reinterpret_cast<uint32_t*>(&p);
}

// ----------------------------------------------------------------------------
// prep 1: reg_w -> bf16 hi/lo, k = tap*256 + c ordering
// ----------------------------------------------------------------------------
__global__ __launch_bounds__(256) void prep_w_kernel(const float* __restrict__ reg_w) {
    int i = blockIdx.x * 256 + threadIdx.x;
    if (i >= C2n * Ktot) return;
    int co = i / Ktot;
    int k = i - co * Ktot;
    int tap = k >> 8;
    int c = k & 255;
    float v = reg_w[((size_t)co * Cn + c) * 9 + tap];
    __nv_bfloat16 h = __float2bfloat16(v);
    g_whi[i] = h;
    g_wlo[i] = __float2bfloat16(v - __bfloat162float(h));
}

// ----------------------------------------------------------------------------
// prep 2: offset_w (18) + mod_w (9) packed as 32 output rows, same k order
// ----------------------------------------------------------------------------
__global__ __launch_bounds__(256) void prep_wom_kernel(
    const float* __restrict__ offset_w, const float* __restrict__ mod_w) {
    int i = blockIdx.x * 256 + threadIdx.x;
    if (i >= 32 * Ktot) return;
    int j = i / Ktot;
    int k = i - j * Ktot;
    int tap = k >> 8;
    int c = k & 255;
    float v = 0.f;
    if (j < 18)      v = offset_w[((size_t)j * Cn + c) * 9 + tap];
    else if (j < 27) v = mod_w[((size_t)(j - 18) * Cn + c) * 9 + tap];
    __nv_bfloat16 h = __float2bfloat16(v);
    g_omhi[i] = h;
    g_omlo[i] = __float2bfloat16(v - __bfloat162float(h));
}

// ----------------------------------------------------------------------------
// prep 3: NCHW fp32 x -> NHWC bf16 hi/lo (xt[b][y][w][c])
// ----------------------------------------------------------------------------
__global__ __launch_bounds__(256) void prep_xt_kernel(const float* __restrict__ x) {
    extern __shared__ float tile[];   // 256 * 65 floats
    const int t = threadIdx.x;
    const int b = blockIdx.x >> 6;
    const int y = blockIdx.x & 63;
    const float* xs = x + (size_t)b * Cn * HWn + y * Wn;
    for (int i = t; i < 16384; i += 256) {
        int c = i >> 6;
        int w = i & 63;
        tile[c * 65 + w] = xs[(size_t)c * HWn + w];
    }
    __syncthreads();
    const size_t obase = ((size_t)(b * 64 + y) * 64) * 256;
    for (int i = t; i < 16384; i += 256) {
        int c = i & 255;
        int w = i >> 8;
        float v = tile[c * 65 + w];
        __nv_bfloat16 h = __float2bfloat16(v);
        g_xhi[obase + (size_t)w * 256 + c] = h;
        g_xlo[obase + (size_t)w * 256 + c] = __float2bfloat16(v - __bfloat162float(h));
    }
}

// ----------------------------------------------------------------------------
// Kernel A: offset + modulator conv as mma GEMM (N=32 incl. 5 pad rows).
// (unchanged from R6 — passes, 95us)
// ----------------------------------------------------------------------------
#define OA_HI 0
#define OA_LO 16384
#define OB_HI 32768
#define OB_LO 36864

__global__ __launch_bounds__(256, 2) void offmask_mma_kernel(
    const float* __restrict__ offset_b, const float* __restrict__ mod_b)
{
    __shared__ __align__(16) char osm[40960];
    const uint32_t osb = smem_to_u32(osm);
    const int t = threadIdx.x;

    const int tile = blockIdx.x;       // 256 tiles
    const int b    = tile >> 5;
    const int sb   = (tile & 31) * 128;

    const int wid  = t >> 5;
    const int lane = t & 31;
    const int wm   = wid & 3;
    const int wn   = wid >> 2;

    const uint32_t lxor = (uint32_t)((lane & 7) << 4);
    const uint32_t asel = (lane & 16) ? 16u : 0u;
    const uint32_t bsel = (lane & 8) ? 16u : 0u;
    const uint32_t aAddrH = osb + OA_HI + (uint32_t)((wm * 32 + (lane & 15)) * 128);
    const uint32_t aAddrL = osb + OA_LO + (uint32_t)((wm * 32 + (lane & 15)) * 128);
    const uint32_t bAddrH = osb + OB_HI + (uint32_t)(((wn * 16 + (lane & 7) + ((lane & 16) ? 8 : 0))) * 128);
    const uint32_t bAddrL = osb + OB_LO + (uint32_t)(((wn * 16 + (lane & 7) + ((lane & 16) ? 8 : 0))) * 128);

    const int spx = t >> 1;
    const int ch  = (t & 1) * 32;
    const int ssp = sb + spx;
    const int sy  = ssp >> 6;
    const int sxw = ssp & 63;
    const uint32_t arow = (uint32_t)(spx * 128);
    const uint32_t pxor2 = (uint32_t)((spx & 7) << 4);

    float d[2][2][4];
#pragma unroll
    for (int mt = 0; mt < 2; mt++)
#pragma unroll
        for (int nt = 0; nt < 2; nt++)
#pragma unroll
            for (int j = 0; j < 4; j++) d[mt][nt][j] = 0.f;

#pragma unroll 1
    for (int kb = 0; kb < 36; kb++) {
        const int tap = kb >> 2;
        const int c0  = (kb & 3) * 64;
        const int kbase = kb * 64;

        __syncthreads();

        // stage B: 32 j x 64 k (128 B/row), hi + lo
        {
            int j  = t >> 3;
            int ku = t & 7;
            uint32_t dst = (uint32_t)(j * 128 + ((ku * 16) ^ ((j & 7) << 4)));
            *(uint4*)(osm + OB_HI + dst) = *(const uint4*)(g_omhi + (size_t)j * Ktot + kbase + ku * 8);
            *(uint4*)(osm + OB_LO + dst) = *(const uint4*)(g_omlo + (size_t)j * Ktot + kbase + ku * 8);
        }

        // stage A: regular shifted taps from NHWC xt (coalesced)
        {
            const int py  = sy + tap / 3 - 1;
            const int pxx = sxw + tap % 3 - 1;
            const bool valid = ((unsigned)py < (unsigned)Hn) && ((unsigned)pxx < (unsigned)Wn);
            if (valid) {
                const size_t src = ((size_t)(b * 4096 + py * 64 + pxx)) * 256 + c0 + ch;
                const uint4* ph = (const uint4*)(g_xhi + src);
                const uint4* pl = (const uint4*)(g_xlo + src);
#pragma unroll
                for (int u = 0; u < 4; u++) {
                    uint32_t o = (uint32_t)((ch * 2 + u * 16) ^ pxor2);
                    *(uint4*)(osm + OA_HI + arow + o) = ph[u];
                    *(uint4*)(osm + OA_LO + arow + o) = pl[u];
                }
            } else {
                uint4 z = make_uint4(0, 0, 0, 0);
#pragma unroll
                for (int u = 0; u < 4; u++) {
                    uint32_t o = (uint32_t)((ch * 2 + u * 16) ^ pxor2);
                    *(uint4*)(osm + OA_HI + arow + o) = z;
                    *(uint4*)(osm + OA_LO + arow + o) = z;
                }
            }
        }

        __syncthreads();

#pragma unroll
        for (int ks = 0; ks < 4; ks++) {
            const uint32_t acol = (uint32_t)((ks * 32 + asel) ^ lxor);
            const uint32_t bcol = (uint32_t)((ks * 32 + bsel) ^ lxor);
            uint32_t Ah[2][4], Al[2][4], BH[4], BL[4];
#pragma unroll
            for (int mt = 0; mt < 2; mt++) {
                ldsm4(aAddrH + mt * 2048 + acol, Ah[mt]);
                ldsm4(aAddrL + mt * 2048 + acol, Al[mt]);
            }
            ldsm4(bAddrH + bcol, BH);
            ldsm4(bAddrL + bcol, BL);
#pragma unroll
            for (int mt = 0; mt < 2; mt++)
#pragma unroll
                for (int nt = 0; nt < 2; nt++) {
                    mma16816(d[mt][nt], Ah[mt], &BH[nt * 2]);
                    mma16816(d[mt][nt], Al[mt], &BH[nt * 2]);
                    mma16816(d[mt][nt], Ah[mt], &BL[nt * 2]);
                }
        }
    }

    {
        const int g   = lane >> 2;
        const int tig = lane & 3;
#pragma unroll
        for (int mt = 0; mt < 2; mt++) {
#pragma unroll
            for (int nt = 0; nt < 2; nt++) {
#pragma unroll
                for (int r = 0; r < 4; r++) {
                    int px = wm * 32 + mt * 16 + g + ((r >= 2) ? 8 : 0);
                    int j  = wn * 16 + nt * 8 + tig * 2 + (r & 1);
                    int sp = sb + px;
                    float v = d[mt][nt][r];
                    if (j < 18) {
                        float o = fminf(16.f, fmaxf(-16.f, v + offset_b[j]));
                        g_offset[(size_t)(b * 18 + j) * HWn + sp] = o;
                    } else if (j < 27) {
                        float o = v + mod_b[j - 18];
                        g_mask[(size_t)(b * 9 + (j - 18)) * HWn + sp] = 1.f / (1.f + expf(-o));
                    }
                }
            }
        }
    }
}

// ----------------------------------------------------------------------------
// Kernel B: deformable conv GEMM, 2 CTAs/SM. CTA = 256 threads = 8 warps
// (1M x 8N), tile M=64 px x N=256 co, K in blocks of 32 (tap x 32c).
// Rows are 128 B = [hi 32k | lo 32k], SW128-style swizzle.
// ----------------------------------------------------------------------------
#define DF_TIDX 0
#define DF_TW   9216
#define DF_A    18432
#define DF_B    26624
#define DF_SMEM 59392

__global__ __launch_bounds__(256, 2)
void dfconv_mma_kernel(float* __restrict__ out)
{
    extern __shared__ __align__(16) char smem[];
    const uint32_t smem_base = smem_to_u32(smem);
    const int t = threadIdx.x;

    const int tile = blockIdx.x;        // 512 tiles
    const int b    = tile >> 6;
    const int sb   = (tile & 63) * 64;  // spatial base (one half-row pair)

    // --- bilinear tables: 64 px x 9 taps ---
    int4*   tbl_idx = (int4*)(smem + DF_TIDX);
    float4* tbl_w   = (float4*)(smem + DF_TW);
    for (int e = t; e < 576; e += 256) {
        int p   = e / 9;
        int tap = e - p * 9;
        int sp  = sb + p;
        int y   = sp >> 6;
        int xw  = sp & 63;
        float dy = g_offset[(size_t)(b * 18 + 2 * tap) * HWn + sp];
        float dx = g_offset[(size_t)(b * 18 + 2 * tap + 1) * HWn + sp];
        float m  = g_mask[(size_t)(b * 9 + tap) * HWn + sp];
        float py = dy + (float)(tap / 3) + (float)(y - 1);
        float px = dx + (float)(tap % 3) + (float)(xw - 1);
        float y0f = floorf(py), x0f = floorf(px);
        float ly = py - y0f, lx = px - x0f;
        int y0 = (int)y0f, x0 = (int)x0f;
        int y1 = y0 + 1, x1 = x0 + 1;
        float vy0 = ((unsigned)y0 < (unsigned)Hn) ? 1.f : 0.f;
        float vy1 = ((unsigned)y1 < (unsigned)Hn) ? 1.f : 0.f;
        float vx0 = ((unsigned)x0 < (unsigned)Wn) ? 1.f : 0.f;
        float vx1 = ((unsigned)x1 < (unsigned)Wn) ? 1.f : 0.f;
        float w00 = (1.f - ly) * (1.f - lx) * m * vy0 * vx0;
        float w01 = (1.f - ly) * lx        * m * vy0 * vx1;
        float w10 = ly        * (1.f - lx) * m * vy1 * vx0;
        float w11 = ly        * lx         * m * vy1 * vx1;
        int cy0 = min(max(y0, 0), Hn - 1), cy1 = min(max(y1, 0), Hn - 1);
        int cx0 = min(max(x0, 0), Wn - 1), cx1 = min(max(x1, 0), Wn - 1);
        tbl_w[e]   = make_float4(w00, w01, w10, w11);
        tbl_idx[e] = make_int4(cy0 * Wn + cx0, cy0 * Wn + cx1,
                               cy1 * Wn + cx0, cy1 * Wn + cx1);
    }

    // gather role: px (64) x 4 subs of 8 channels
    const int gpx = t >> 2;
    const int sub = t & 3;
    const uint32_t grow = (uint32_t)(gpx * 128);
    const uint32_t pxor = (uint32_t)((gpx & 7) << 4);

    // mma role: 8 warps, warp tile 64(M) x 32(N)
    const int wid  = t >> 5;
    const int lane = t & 31;
    const int wn   = wid;
    const uint32_t lxor = (uint32_t)((lane & 7) << 4);
    const uint32_t asel = (lane & 16) ? 16u : 0u;
    const uint32_t bsel = (lane & 8) ? 16u : 0u;
    const uint32_t aAddr = smem_base + DF_A + (uint32_t)((lane & 15) * 128);
    const uint32_t bAddr = smem_base + DF_B
        + (uint32_t)((wn * 32 + (lane & 7) + ((lane & 16) ? 8 : 0)) * 128);

    float d[4][4][4];
#pragma unroll
    for (int mt = 0; mt < 4; mt++)
#pragma unroll
        for (int nt = 0; nt < 4; nt++)
#pragma unroll
            for (int j = 0; j < 4; j++) d[mt][nt][j] = 0.f;

#pragma unroll 1
    for (int kb = 0; kb < 72; kb++) {
        const int tap = kb >> 3;
        const int c0  = (kb & 7) * 32;
        const int kbase = kb * 32;

        __syncthreads();

        // --- stage B tile: 256 co x 32 k, row = [hi 64B | lo 64B] ---
#pragma unroll
        for (int it = 0; it < 4; it++) {
            int ci = t + it * 256;       // 0..1023
            int co = ci >> 2;
            int ku = ci & 3;
            uint32_t ch = (uint32_t)(ku * 16);
            uint32_t dst = (uint32_t)(co * 128);
            *(uint4*)(smem + DF_B + dst + (ch ^ ((co & 7) << 4))) =
                *(const uint4*)(g_whi + (size_t)co * Ktot + kbase + ku * 8);
            *(uint4*)(smem + DF_B + dst + ((64 + ch) ^ ((co & 7) << 4))) =
                *(const uint4*)(g_wlo + (size_t)co * Ktot + kbase + ku * 8);
        }

        // --- gather A: 64 px x 32 c bilinear, row = [hi 64B | lo 64B] ---
        {
            int4   id = tbl_idx[gpx * 9 + tap];
            float4 wt = tbl_w[gpx * 9 + tap];
            const size_t cbase = ((size_t)b * 4096) * 256 + c0 + sub * 8;
            const size_t o0 = cbase + (size_t)id.x * 256;
            const size_t o1 = cbase + (size_t)id.y * 256;
            const size_t o2 = cbase + (size_t)id.z * 256;
            const size_t o3 = cbase + (size_t)id.w * 256;
            float v[8];
#pragma unroll
            for (int i = 0; i < 8; i++) v[i] = 0.f;
            accum8(v, *(const uint4*)(g_xhi + o0), *(const uint4*)(g_xlo + o0), wt.x);
            accum8(v, *(const uint4*)(g_xhi + o1), *(const uint4*)(g_xlo + o1), wt.y);
            accum8(v, *(const uint4*)(g_xhi + o2), *(const uint4*)(g_xlo + o2), wt.z);
            accum8(v, *(const uint4*)(g_xhi + o3), *(const uint4*)(g_xlo + o3), wt.w);
            float r[8];
            uint4 H, L;
            H.x = pack_hi(v[0], v[1], r[0], r[1]);
            H.y = pack_hi(v[2], v[3], r[2], r[3]);
            H.z = pack_hi(v[4], v[5], r[4], r[5]);
            H.w = pack_hi(v[6], v[7], r[6], r[7]);
            L.x = pack_bf2(r[0], r[1]);
            L.y = pack_bf2(r[2], r[3]);
            L.z = pack_bf2(r[4], r[5]);
            L.w = pack_bf2(r[6], r[7]);
            *(uint4*)(smem + DF_A + grow + ((sub * 16) ^ pxor)) = H;
            *(uint4*)(smem + DF_A + grow + ((64 + sub * 16) ^ pxor)) = L;
        }

        __syncthreads();

        // --- mma: 2 k16-steps x (Ah*Bh + Al*Bh + Ah*Bl) ---
#pragma unroll
        for (int ks = 0; ks < 2; ks++) {
            const uint32_t acolH = (uint32_t)((ks * 32 + asel) ^ lxor);
            const uint32_t acolL = (uint32_t)((64 + ks * 32 + asel) ^ lxor);
            const uint32_t bcolH = (uint32_t)((ks * 32 + bsel) ^ lxor);
            const uint32_t bcolL = (uint32_t)((64 + ks * 32 + bsel) ^ lxor);
            uint32_t Ah[4][4], Al[4][4], Bf[2][4];
#pragma unroll
            for (int mt = 0; mt < 4; mt++) {
                ldsm4(aAddr + mt * 2048 + acolH, Ah[mt]);
                ldsm4(aAddr + mt * 2048 + acolL, Al[mt]);
            }
            ldsm4(bAddr + bcolH, Bf[0]);
            ldsm4(bAddr + 2048 + bcolH, Bf[1]);
#pragma unroll
            for (int mt = 0; mt < 4; mt++)
#pragma unroll
                for (int nt = 0; nt < 4; nt++) {
                    const uint32_t* bp = &Bf[nt >> 1][(nt & 1) * 2];
                    mma16816(d[mt][nt], Ah[mt], bp);
                    mma16816(d[mt][nt], Al[mt], bp);
                }
            ldsm4(bAddr + bcolL, Bf[0]);
            ldsm4(bAddr + 2048 + bcolL, Bf[1]);
#pragma unroll
            for (int mt = 0; mt < 4; mt++)
#pragma unroll
                for (int nt = 0; nt < 4; nt++) {
                    const uint32_t* bp = &Bf[nt >> 1][(nt & 1) * 2];
                    mma16816(d[mt][nt], Ah[mt], bp);
                }
        }
    }

    // --- epilogue: d[mt][nt] -> out[b][co][sb + px] ---
    {
        const int g   = lane >> 2;
        const int tig = lane & 3;
        float* outb = out + (size_t)b * C2n * HWn + sb;
#pragma unroll
        for (int mt = 0; mt < 4; mt++) {
            const int px0 = mt * 16 + g;
#pragma unroll
            for (int nt = 0; nt < 4; nt++) {
                const int co0 = wn * 32 + nt * 8 + tig * 2;
                outb[(size_t)co0 * HWn + px0]           = d[mt][nt][0];
                outb[(size_t)(co0 + 1) * HWn + px0]     = d[mt][nt][1];
                outb[(size_t)co0 * HWn + px0 + 8]       = d[mt][nt][2];
                outb[(size_t)(co0 + 1) * HWn + px0 + 8] = d[mt][nt][3];
            }
        }
    }
}

// ----------------------------------------------------------------------------
extern "C" void kernel_launch(void* const* d_in, const int* in_sizes, int n_in,
                              void* d_out, int out_size)
{
    const float* x        = (const float*)d_in[0];
    const float* offset_w = (const float*)d_in[1];
    const float* offset_b = (const float*)d_in[2];
    const float* mod_w    = (const float*)d_in[3];
    const float* mod_b    = (const float*)d_in[4];
    const float* reg_w    = (const float*)d_in[5];
    float* out = (float*)d_out;

    cudaFuncSetAttribute(dfconv_mma_kernel,
                         cudaFuncAttributeMaxDynamicSharedMemorySize, DF_SMEM);
    cudaFuncSetAttribute(prep_xt_kernel,
                         cudaFuncAttributeMaxDynamicSharedMemorySize, 256 * 65 * 4);

    prep_w_kernel<<<(C2n * Ktot + 255) / 256, 256>>>(reg_w);
    prep_wom_kernel<<<(32 * Ktot + 255) / 256, 256>>>(offset_w, mod_w);
    prep_xt_kernel<<<512, 256, 256 * 65 * 4>>>(x);
    offmask_mma_kernel<<<256, 256>>>(offset_b, mod_b);
    dfconv_mma_kernel<<<512, 256, DF_SMEM>>>(out);
}